// round 9
// baseline (speedup 1.0000x reference)
#include <cuda_runtime.h>
#include <cuda_bf16.h>
#include <cstdint>

// Problem constants
#define G   7
#define BSZ 8
#define MSZ 512
#define NSZ 512
#define KSZ 1024
// x zp = -66, y zp = 160. Sign-flip y: y' = y - 128. Then
//   out = s * ( D - 32*Rx + 66*Cy' + C0 ),  D = sum x*y', C0 = -32*66*1024
#define C0F (-2162688.0f)

#define XELEMS ((size_t)G * BSZ * MSZ * KSZ)   // 29360128
#define YELEMS ((size_t)BSZ * KSZ * NSZ)       // 4194304

// ---- arch-specific feature gate (tcgen05 only legal on sm_103a pass) ----
#if defined(__CUDA_ARCH_FEAT_SM103_ALL) || \
    (defined(__CUDA_ARCH_SPECIFIC__) && (__CUDA_ARCH_SPECIFIC__ == 1030)) || \
    (defined(__CUDA_ARCH_FAMILY_SPECIFIC__) && (__CUDA_ARCH_FAMILY_SPECIFIC__ == 1030))
#define TC_OK 1
#endif

// ---------------- tcgen05 bf16 GEMM tiling ----------------
#define BMG 128
#define BNG 256
#define BKE 64              // K elems per stage (128B bf16 rows)
#define NSTG (KSZ / BKE)    // 16
#define SM_A(buf)  ((buf) * 16384)            // 2 x 16KB
#define SM_B(buf)  (32768 + (buf) * 32768)    // 2 x 32KB
#define SM_TMEMP   98304
#define SM_MBAR0   98320
#define SM_MBAR1   98328
#define SM_CYS     98336                      // 256 x float
#define SM_ONES    99392                      // 8 rows x 128B bf16 ones
#define DSMEM_TC   100480

// Scratch (allocation-free: __device__ globals)
__device__ __align__(16) uint16_t g_xb[XELEMS];   // x bf16 [z][m][k]
__device__ __align__(16) uint16_t g_ytb[YELEMS];  // y' transposed bf16 [b][n][k]
__device__ int g_Cy[BSZ * NSZ];                   // int col sums of y' (atomic)
__device__ int g_xfmt;
__device__ int g_yfmt;

// ---------------------------------------------------------------------------
// helpers
// ---------------------------------------------------------------------------
__device__ __forceinline__ uint32_t smem_u32(const void* p) {
    uint32_t a;
    asm("{ .reg .u64 t; cvta.to.shared.u64 t, %1; cvt.u32.u64 %0, t; }" : "=r"(a) : "l"(p));
    return a;
}
__device__ __forceinline__ void cp16(uint32_t dst, const void* src) {
    asm volatile("cp.async.cg.shared.global [%0], [%1], 16;" :: "r"(dst), "l"(src));
}
__device__ __forceinline__ uint32_t pack_bf16(float lo, float hi) {
    __nv_bfloat162 h = __floats2bfloat162_rn(lo, hi);
    return *(uint32_t*)&h;
}

// ---------------------------------------------------------------------------
// Kernel 0: probe input encodings (int32-materialized vs raw bytes)
// ---------------------------------------------------------------------------
__global__ void probe_kernel(const void* x, const void* y) {
    if (threadIdx.x == 0 && blockIdx.x == 0) {
        const int* xi = (const int*)x;
        int ok = 1;
        for (int i = 0; i < 256; i++) { int v = xi[i]; if (v < -128 || v > 127) { ok = 0; break; } }
        g_xfmt = ok;
        const int* yi = (const int*)y;
        ok = 1;
        for (int i = 0; i < 256; i++) { int v = yi[i]; if (v < 0 || v > 255) { ok = 0; break; } }
        g_yfmt = ok;
    }
}

// ---------------------------------------------------------------------------
// Kernel 1: x -> bf16, conversion ONLY (rowsum now comes from the ones-MMA).
// 16 elems/thread, fully coalesced.
// ---------------------------------------------------------------------------
__global__ __launch_bounds__(256) void repack_x(const void* __restrict__ xin) {
    size_t base = (size_t)blockIdx.x * 1024;   // int4 index base (1024 int4/block)
    int t = threadIdx.x;
    if (g_xfmt) {
        const int4* src = (const int4*)xin;
        uint2* dst = (uint2*)g_xb;
        #pragma unroll
        for (int i = 0; i < 4; i++) {
            size_t idx = base + t + i * 256;
            int4 v = src[idx];
            uint2 o;
            o.x = pack_bf16((float)v.x, (float)v.y);
            o.y = pack_bf16((float)v.z, (float)v.w);
            dst[idx] = o;
        }
    } else {
        const uint32_t* src = (const uint32_t*)xin;
        uint2* dst = (uint2*)g_xb;
        #pragma unroll
        for (int i = 0; i < 4; i++) {
            size_t idx = base + t + i * 256;
            uint32_t v = src[idx];
            uint2 o;
            o.x = pack_bf16((float)(int)(int8_t)(v), (float)(int)(int8_t)(v >> 8));
            o.y = pack_bf16((float)(int)(int8_t)(v >> 16), (float)(int)(int8_t)(v >> 24));
            dst[idx] = o;
        }
    }
}

// ---------------------------------------------------------------------------
// Kernel 2: transpose y [b][k][n] -> g_ytb [b][n][k] bf16 (y-128),
//           FUSED col sums (int atomics -> deterministic). g_Cy pre-zeroed.
// ---------------------------------------------------------------------------
__global__ __launch_bounds__(256) void transpose_y_kernel(const void* __restrict__ yin) {
    __shared__ __align__(16) uint8_t s[32][136];
    __shared__ int csum[128];
    int b  = blockIdx.z;
    int n0 = blockIdx.x * 128;
    int k0 = blockIdx.y * 32;
    int t  = threadIdx.x;
    int fmt = g_yfmt;

    if (t < 128) csum[t] = 0;

    #pragma unroll
    for (int i = 0; i < 4; i++) {
        int w  = t + i * 256;
        int k  = w >> 5;
        int nw = w & 31;
        size_t base = ((size_t)(b * KSZ + k0 + k)) * NSZ + n0 + nw * 4;
        uint32_t wv;
        if (fmt) {
            int4 v = *(const int4*)((const int*)yin + base);
            wv = (v.x & 0xff) | ((v.y & 0xff) << 8) | ((v.z & 0xff) << 16) | ((uint32_t)(v.w & 0xff) << 24);
        } else {
            wv = *(const uint32_t*)((const uint8_t*)yin + base);
        }
        *(uint32_t*)&s[k][nw * 4] = wv;
    }
    __syncthreads();
    #pragma unroll
    for (int i = 0; i < 4; i++) {
        int w  = t + i * 256;
        int n  = w >> 3;
        int kq = w & 7;
        uint32_t v = (uint32_t)s[kq * 4 + 0][n]
                   | ((uint32_t)s[kq * 4 + 1][n] << 8)
                   | ((uint32_t)s[kq * 4 + 2][n] << 16)
                   | ((uint32_t)s[kq * 4 + 3][n] << 24);
        uint32_t vp = v ^ 0x80808080u;                 // bytes now s8 y' = y-128
        atomicAdd(&csum[n], __dp4a((int)vp, 0x01010101, 0));
        uint2 o;
        o.x = pack_bf16((float)(int)(int8_t)(vp), (float)(int)(int8_t)(vp >> 8));
        o.y = pack_bf16((float)(int)(int8_t)(vp >> 16), (float)(int)(int8_t)(vp >> 24));
        *(uint2*)(g_ytb + ((size_t)(b * NSZ + n0 + n)) * KSZ + k0 + kq * 4) = o;
    }
    __syncthreads();
    if (t < 128) atomicAdd(&g_Cy[b * NSZ + n0 + t], csum[t]);
}

// ---------------------------------------------------------------------------
// Kernel 3: tcgen05 bf16 GEMM + ones-MMA row sums. Tile 128(M) x 256(N).
// ---------------------------------------------------------------------------
#ifdef TC_OK
__device__ __forceinline__ uint32_t sw128(uint32_t off) { return off ^ ((off >> 3) & 0x70); }
__device__ __forceinline__ uint32_t elect_one() {
    uint32_t p;
    asm volatile("{\n\t.reg .pred P;\n\telect.sync _|P, 0xFFFFFFFF;\n\tselp.b32 %0, 1, 0, P;\n\t}" : "=r"(p));
    return p;
}
__device__ __forceinline__ void mbar_init(uint32_t a, uint32_t cnt) {
    asm volatile("mbarrier.init.shared.b64 [%0], %1;" :: "r"(a), "r"(cnt) : "memory");
}
__device__ __forceinline__ void mbar_wait(uint32_t a, uint32_t parity) {
    asm volatile(
        "{\n\t.reg .pred P;\n\t"
        "W%=:\n\t"
        "mbarrier.try_wait.parity.acquire.cta.shared::cta.b64 P, [%0], %1, 0x989680;\n\t"
        "@P bra D%=;\n\t"
        "bra W%=;\n\t"
        "D%=:\n\t}"
        :: "r"(a), "r"(parity) : "memory");
}
__device__ __forceinline__ uint64_t smem_desc(uint32_t addr) {
    const uint64_t base = (uint64_t(2) << 61) | (uint64_t(1) << 46) | (uint64_t(64) << 32) | (uint64_t(1) << 16);
    return base | ((uint64_t)(addr >> 4) & 0x3FFF);
}
// idesc kind::f16 bf16: dtype F32(1)<<4, atype BF16(1)<<7, btype BF16(1)<<10
#define IDESC_MAIN ((1u << 4) | (1u << 7) | (1u << 10) | ((BNG / 8) << 17) | ((BMG / 16) << 24))
#define IDESC_ONES ((1u << 4) | (1u << 7) | (1u << 10) | (1u << 17) | ((BMG / 16) << 24))
__device__ __forceinline__ void mma_bf16(uint32_t d, uint64_t ad, uint64_t bd, uint32_t idesc, uint32_t en) {
    asm volatile(
        "{\n\t.reg .pred p;\n\tsetp.ne.u32 p, %5, 0;\n\t"
        "tcgen05.mma.cta_group::1.kind::f16 [%0], %1, %2, %3, {%4, %4, %4, %4}, p;\n\t}"
        :: "r"(d), "l"(ad), "l"(bd), "r"(idesc), "r"(0u), "r"(en) : "memory");
}
#endif

__global__ __launch_bounds__(128, 2) void gemm_tc(const float* __restrict__ xs,
                                                  const float* __restrict__ ys,
                                                  float* __restrict__ out) {
#ifdef TC_OK
    extern __shared__ __align__(1024) uint8_t smem[];
    const uint32_t sb = smem_u32(smem);
    const int t = threadIdx.x, wid = t >> 5, lane = t & 31;
    const int z = blockIdx.z, b = z & 7;
    const int m0 = blockIdx.y * BMG;
    const int n0 = blockIdx.x * BNG;

    const uint16_t* xa = g_xb  + (size_t)z * MSZ * KSZ + (size_t)m0 * KSZ;
    const uint16_t* yb = g_ytb + (size_t)b * NSZ * KSZ + (size_t)n0 * KSZ;

    auto loadstage = [&](int s, int buf) {
        uint32_t ab = sb + SM_A(buf);
        uint32_t bbse = sb + SM_B(buf);
        #pragma unroll
        for (int i = 0; i < 8; i++) {          // A: 128 rows x 128B
            int id = t + i * 128;
            int row = id >> 3, c = (id & 7) << 4;
            cp16(ab + sw128(row * 128 + c), (const uint8_t*)(xa + (size_t)row * KSZ + s * BKE) + c);
        }
        #pragma unroll
        for (int i = 0; i < 16; i++) {         // B: 256 rows x 128B
            int id = t + i * 128;
            int row = id >> 3, c = (id & 7) << 4;
            cp16(bbse + sw128(row * 128 + c), (const uint8_t*)(yb + (size_t)row * KSZ + s * BKE) + c);
        }
        asm volatile("cp.async.commit_group;" ::: "memory");
    };

    // issue first stage BEFORE the (possibly blocking) TMEM alloc
    loadstage(0, 0);

    if (wid == 0) {
        asm volatile("tcgen05.alloc.cta_group::1.sync.aligned.shared::cta.b32 [%0], %1;"
                     :: "r"(sb + SM_TMEMP), "r"(512u) : "memory");
        asm volatile("tcgen05.relinquish_alloc_permit.cta_group::1.sync.aligned;" ::: "memory");
    }
    if (t == 0) { mbar_init(sb + SM_MBAR0, 1); mbar_init(sb + SM_MBAR1, 1); }
    // fill ones tile: 1024B of bf16 1.0 (0x3F80)
    {
        uint32_t* op = (uint32_t*)(smem + SM_ONES);
        op[t] = 0x3F803F80u;
        op[t + 128] = 0x3F803F80u;
    }
    __syncthreads();
    uint32_t tmem;
    asm volatile("ld.shared.b32 %0, [%1];" : "=r"(tmem) : "r"(sb + SM_TMEMP));

    int ph0 = 0, ph1 = 0;
    const uint64_t ones_desc = smem_desc(sb + SM_ONES);

    for (int s = 0; s < NSTG; s++) {
        const int buf = s & 1;
        if (s + 1 < NSTG) {
            const int nb = buf ^ 1;
            if (s + 1 >= 2) {    // nb consumed by mma of stage s-1
                if (nb == 0) { mbar_wait(sb + SM_MBAR0, ph0); ph0 ^= 1; }
                else         { mbar_wait(sb + SM_MBAR1, ph1); ph1 ^= 1; }
            }
            loadstage(s + 1, nb);
            asm volatile("cp.async.wait_group 1;" ::: "memory");
        } else {
            asm volatile("cp.async.wait_group 0;" ::: "memory");
        }
        __syncthreads();
        asm volatile("fence.proxy.async.shared::cta;" ::: "memory");

        if (wid == 0) {
            asm volatile("tcgen05.fence::after_thread_sync;" ::: "memory");
            if (elect_one()) {
                uint64_t ad = smem_desc(sb + SM_A(buf));
                uint64_t bd = smem_desc(sb + SM_B(buf));
                #pragma unroll
                for (int k = 0; k < 4; k++) {  // 4 x K=16 per 128B stage
                    uint32_t en = (uint32_t)(s * 4 + k);
                    mma_bf16(tmem, ad + k * 2, bd + k * 2, IDESC_MAIN, en);
                    mma_bf16(tmem + 256, ad + k * 2, ones_desc + k * 2, IDESC_ONES, en);
                }
                asm volatile("tcgen05.commit.cta_group::1.mbarrier::arrive::one.shared::cluster.b64 [%0];"
                             :: "r"(sb + (buf ? SM_MBAR1 : SM_MBAR0)) : "memory");
            }
        }
    }

    // stage 15 used buf1; its commit covers all prior mma
    mbar_wait(sb + SM_MBAR1, ph1);
    asm volatile("tcgen05.fence::after_thread_sync;" ::: "memory");

    // corrections: Rx from TMEM col 256 (exact fp32 int), Cy from int atomics
    float* cys = (float*)(smem + SM_CYS);     // 66*Cy + C0
    cys[t]       = fmaf(66.0f, (float)g_Cy[b * NSZ + n0 + t], C0F);
    cys[t + 128] = fmaf(66.0f, (float)g_Cy[b * NSZ + n0 + 128 + t], C0F);

    uint32_t rxu;
    asm volatile("tcgen05.ld.sync.aligned.32x32b.x1.b32 {%0}, [%1];"
                 : "=r"(rxu) : "r"(tmem + 256));
    asm volatile("tcgen05.wait::ld.sync.aligned;" ::: "memory");
    const float rx32 = -32.0f * __uint_as_float(rxu);
    __syncthreads();

    const float sc = xs[0] * ys[0];
    float* tile = (float*)(smem + wid * 4352);   // per-warp 32x33 transpose tile

    #pragma unroll 1
    for (int chunk = 0; chunk < BNG / 32; chunk++) {
        uint32_t d[32];
        asm volatile(
            "tcgen05.ld.sync.aligned.32x32b.x32.b32 "
            "{%0,%1,%2,%3,%4,%5,%6,%7,%8,%9,%10,%11,%12,%13,%14,%15,"
            "%16,%17,%18,%19,%20,%21,%22,%23,%24,%25,%26,%27,%28,%29,%30,%31}, [%32];"
            : "=r"(d[0]), "=r"(d[1]), "=r"(d[2]), "=r"(d[3]), "=r"(d[4]), "=r"(d[5]), "=r"(d[6]), "=r"(d[7]),
              "=r"(d[8]), "=r"(d[9]), "=r"(d[10]), "=r"(d[11]), "=r"(d[12]), "=r"(d[13]), "=r"(d[14]), "=r"(d[15]),
              "=r"(d[16]), "=r"(d[17]), "=r"(d[18]), "=r"(d[19]), "=r"(d[20]), "=r"(d[21]), "=r"(d[22]), "=r"(d[23]),
              "=r"(d[24]), "=r"(d[25]), "=r"(d[26]), "=r"(d[27]), "=r"(d[28]), "=r"(d[29]), "=r"(d[30]), "=r"(d[31])
            : "r"(tmem + chunk * 32));
        asm volatile("tcgen05.wait::ld.sync.aligned;" ::: "memory");

        #pragma unroll
        for (int c = 0; c < 32; c++) {
            float fd = __uint_as_float(d[c]);
            tile[lane * 33 + c] = sc * (fd + rx32 + cys[chunk * 32 + c]);
        }
        __syncwarp();
        #pragma unroll
        for (int r = 0; r < 32; r++) {
            out[((size_t)z * MSZ + m0 + wid * 32 + r) * NSZ + n0 + chunk * 32 + lane] = tile[r * 33 + lane];
        }
        __syncwarp();
    }

    __syncthreads();
    if (wid == 0) {
        asm volatile("tcgen05.dealloc.cta_group::1.sync.aligned.b32 %0, %1;" :: "r"(tmem), "r"(512u));
    }
#endif
}

// ---------------------------------------------------------------------------
extern "C" void kernel_launch(void* const* d_in, const int* in_sizes, int n_in,
                              void* d_out, int out_size) {
    const void* x = nullptr;
    const void* y = nullptr;
    const float* xs = nullptr;
    const float* ys = nullptr;

    for (int i = 0; i < n_in; i++) {
        long sz = in_sizes[i];
        if (sz == (long)XELEMS) x = d_in[i];
        else if (sz == (long)YELEMS) y = d_in[i];
        else if (xs == nullptr) xs = (const float*)d_in[i];
        else if (ys == nullptr) ys = (const float*)d_in[i];
    }
    float* out = (float*)d_out;

    cudaFuncSetAttribute(gemm_tc, cudaFuncAttributeMaxDynamicSharedMemorySize, DSMEM_TC);

    void* cyPtr = nullptr;
    cudaGetSymbolAddress(&cyPtr, g_Cy);

    probe_kernel<<<1, 32>>>(x, y);
    cudaMemsetAsync(cyPtr, 0, BSZ * NSZ * sizeof(int));
    repack_x<<<(int)(XELEMS / 4096), 256>>>(x);
    transpose_y_kernel<<<dim3(NSZ / 128, KSZ / 32, BSZ), 256>>>(y);
    gemm_tc<<<dim3(NSZ / BNG, MSZ / BMG, G * BSZ), 128, DSMEM_TC>>>(xs, ys, out);
}

// round 10
// speedup vs baseline: 1.2238x; 1.2238x over previous
#include <cuda_runtime.h>
#include <cuda_bf16.h>
#include <cstdint>

// Problem constants
#define G   7
#define BSZ 8
#define MSZ 512
#define NSZ 512
#define KSZ 1024
// x zp = -66, y zp = 160.  out = xs*ys * sum_k (x+66)*(y-160)
// x+66 in [-62,193], y-160 in [-160,95]: both EXACT in bf16 -> no corrections.

#define XELEMS ((size_t)G * BSZ * MSZ * KSZ)   // 29360128
#define YELEMS ((size_t)BSZ * KSZ * NSZ)       // 4194304

// ---- arch-specific feature gate (tcgen05 only legal on sm_103a pass) ----
#if defined(__CUDA_ARCH_FEAT_SM103_ALL) || \
    (defined(__CUDA_ARCH_SPECIFIC__) && (__CUDA_ARCH_SPECIFIC__ == 1030)) || \
    (defined(__CUDA_ARCH_FAMILY_SPECIFIC__) && (__CUDA_ARCH_FAMILY_SPECIFIC__ == 1030))
#define TC_OK 1
#endif

// ---------------- tcgen05 bf16 GEMM tiling ----------------
#define BMG 128
#define BNG 256
#define BKE 64              // K elems per stage (128B bf16 rows)
#define NSTG (KSZ / BKE)    // 16
#define SM_A(buf)  ((buf) * 16384)            // 2 x 16KB
#define SM_B(buf)  (32768 + (buf) * 32768)    // 2 x 32KB
#define SM_TMEMP   98304
#define SM_MBAR0   98312
#define SM_MBAR1   98320
#define DSMEM_TC   98336

// Scratch (allocation-free: __device__ globals)
__device__ __align__(16) uint16_t g_xb[XELEMS];   // (x+66) bf16 [z][m][k]
__device__ __align__(16) uint16_t g_ytb[YELEMS];  // (y-160) transposed bf16 [b][n][k]
__device__ int g_xfmt;
__device__ int g_yfmt;

// ---------------------------------------------------------------------------
// helpers
// ---------------------------------------------------------------------------
__device__ __forceinline__ uint32_t smem_u32(const void* p) {
    uint32_t a;
    asm("{ .reg .u64 t; cvta.to.shared.u64 t, %1; cvt.u32.u64 %0, t; }" : "=r"(a) : "l"(p));
    return a;
}
__device__ __forceinline__ void cp16(uint32_t dst, const void* src) {
    asm volatile("cp.async.cg.shared.global [%0], [%1], 16;" :: "r"(dst), "l"(src));
}
__device__ __forceinline__ uint32_t pack_bf16(float lo, float hi) {
    __nv_bfloat162 h = __floats2bfloat162_rn(lo, hi);
    return *(uint32_t*)&h;
}

// ---------------------------------------------------------------------------
// Kernel 0: probe input encodings (int32-materialized vs raw bytes)
// ---------------------------------------------------------------------------
__global__ void probe_kernel(const void* x, const void* y) {
    if (threadIdx.x == 0 && blockIdx.x == 0) {
        const int* xi = (const int*)x;
        int ok = 1;
        for (int i = 0; i < 256; i++) { int v = xi[i]; if (v < -128 || v > 127) { ok = 0; break; } }
        g_xfmt = ok;
        const int* yi = (const int*)y;
        ok = 1;
        for (int i = 0; i < 256; i++) { int v = yi[i]; if (v < 0 || v > 255) { ok = 0; break; } }
        g_yfmt = ok;
    }
}

// ---------------------------------------------------------------------------
// Kernel 1: x -> bf16(x+66). Pure streaming conversion, 16 elems/thread.
// ---------------------------------------------------------------------------
__global__ __launch_bounds__(256) void repack_x(const void* __restrict__ xin) {
    size_t base = (size_t)blockIdx.x * 1024;
    int t = threadIdx.x;
    if (g_xfmt) {
        const int4* src = (const int4*)xin;
        uint2* dst = (uint2*)g_xb;
        #pragma unroll
        for (int i = 0; i < 4; i++) {
            size_t idx = base + t + i * 256;
            int4 v = src[idx];
            uint2 o;
            o.x = pack_bf16((float)(v.x + 66), (float)(v.y + 66));
            o.y = pack_bf16((float)(v.z + 66), (float)(v.w + 66));
            dst[idx] = o;
        }
    } else {
        const uint32_t* src = (const uint32_t*)xin;
        uint2* dst = (uint2*)g_xb;
        #pragma unroll
        for (int i = 0; i < 4; i++) {
            size_t idx = base + t + i * 256;
            uint32_t v = src[idx];
            uint2 o;
            o.x = pack_bf16((float)((int)(int8_t)(v) + 66), (float)((int)(int8_t)(v >> 8) + 66));
            o.y = pack_bf16((float)((int)(int8_t)(v >> 16) + 66), (float)((int)(int8_t)(v >> 24) + 66));
            dst[idx] = o;
        }
    }
}

// ---------------------------------------------------------------------------
// Kernel 2: transpose y [b][k][n] -> g_ytb [b][n][k] = bf16(y - 160)
// ---------------------------------------------------------------------------
__global__ __launch_bounds__(256) void transpose_y_kernel(const void* __restrict__ yin) {
    __shared__ __align__(16) uint8_t s[32][136];
    int b  = blockIdx.z;
    int n0 = blockIdx.x * 128;
    int k0 = blockIdx.y * 32;
    int t  = threadIdx.x;
    int fmt = g_yfmt;

    #pragma unroll
    for (int i = 0; i < 4; i++) {
        int w  = t + i * 256;
        int k  = w >> 5;
        int nw = w & 31;
        size_t base = ((size_t)(b * KSZ + k0 + k)) * NSZ + n0 + nw * 4;
        uint32_t wv;
        if (fmt) {
            int4 v = *(const int4*)((const int*)yin + base);
            wv = (v.x & 0xff) | ((v.y & 0xff) << 8) | ((v.z & 0xff) << 16) | ((uint32_t)(v.w & 0xff) << 24);
        } else {
            wv = *(const uint32_t*)((const uint8_t*)yin + base);
        }
        *(uint32_t*)&s[k][nw * 4] = wv;
    }
    __syncthreads();
    #pragma unroll
    for (int i = 0; i < 4; i++) {
        int w  = t + i * 256;
        int n  = w >> 3;
        int kq = w & 7;
        int e0 = (int)s[kq * 4 + 0][n] - 160;
        int e1 = (int)s[kq * 4 + 1][n] - 160;
        int e2 = (int)s[kq * 4 + 2][n] - 160;
        int e3 = (int)s[kq * 4 + 3][n] - 160;
        uint2 o;
        o.x = pack_bf16((float)e0, (float)e1);
        o.y = pack_bf16((float)e2, (float)e3);
        *(uint2*)(g_ytb + ((size_t)(b * NSZ + n0 + n)) * KSZ + k0 + kq * 4) = o;
    }
}

// ---------------------------------------------------------------------------
// Kernel 3: tcgen05 bf16 GEMM. Tile 128(M) x 256(N). TMEM 256 cols ->
//           two CTAs co-resident per SM (TMEM = 512 cols total).
// ---------------------------------------------------------------------------
#ifdef TC_OK
__device__ __forceinline__ uint32_t sw128(uint32_t off) { return off ^ ((off >> 3) & 0x70); }
__device__ __forceinline__ uint32_t elect_one() {
    uint32_t p;
    asm volatile("{\n\t.reg .pred P;\n\telect.sync _|P, 0xFFFFFFFF;\n\tselp.b32 %0, 1, 0, P;\n\t}" : "=r"(p));
    return p;
}
__device__ __forceinline__ void mbar_init(uint32_t a, uint32_t cnt) {
    asm volatile("mbarrier.init.shared.b64 [%0], %1;" :: "r"(a), "r"(cnt) : "memory");
}
__device__ __forceinline__ void mbar_wait(uint32_t a, uint32_t parity) {
    asm volatile(
        "{\n\t.reg .pred P;\n\t"
        "W%=:\n\t"
        "mbarrier.try_wait.parity.acquire.cta.shared::cta.b64 P, [%0], %1, 0x989680;\n\t"
        "@P bra D%=;\n\t"
        "bra W%=;\n\t"
        "D%=:\n\t}"
        :: "r"(a), "r"(parity) : "memory");
}
__device__ __forceinline__ uint64_t smem_desc(uint32_t addr) {
    const uint64_t base = (uint64_t(2) << 61) | (uint64_t(1) << 46) | (uint64_t(64) << 32) | (uint64_t(1) << 16);
    return base | ((uint64_t)(addr >> 4) & 0x3FFF);
}
// idesc kind::f16 bf16: dtype F32(1)<<4, atype BF16(1)<<7, btype BF16(1)<<10
#define IDESC_MAIN ((1u << 4) | (1u << 7) | (1u << 10) | ((BNG / 8) << 17) | ((BMG / 16) << 24))
__device__ __forceinline__ void mma_bf16(uint32_t d, uint64_t ad, uint64_t bd, uint32_t en) {
    asm volatile(
        "{\n\t.reg .pred p;\n\tsetp.ne.u32 p, %5, 0;\n\t"
        "tcgen05.mma.cta_group::1.kind::f16 [%0], %1, %2, %3, {%4, %4, %4, %4}, p;\n\t}"
        :: "r"(d), "l"(ad), "l"(bd), "r"((uint32_t)IDESC_MAIN), "r"(0u), "r"(en) : "memory");
}
#endif

__global__ __launch_bounds__(128, 2) void gemm_tc(const float* __restrict__ xs,
                                                  const float* __restrict__ ys,
                                                  float* __restrict__ out) {
#ifdef TC_OK
    extern __shared__ __align__(1024) uint8_t smem[];
    const uint32_t sb = smem_u32(smem);
    const int t = threadIdx.x, wid = t >> 5, lane = t & 31;
    const int z = blockIdx.z, b = z & 7;
    const int m0 = blockIdx.y * BMG;
    const int n0 = blockIdx.x * BNG;

    const uint16_t* xa = g_xb  + (size_t)z * MSZ * KSZ + (size_t)m0 * KSZ;
    const uint16_t* yb = g_ytb + (size_t)b * NSZ * KSZ + (size_t)n0 * KSZ;

    auto loadstage = [&](int s, int buf) {
        uint32_t ab = sb + SM_A(buf);
        uint32_t bbse = sb + SM_B(buf);
        #pragma unroll
        for (int i = 0; i < 8; i++) {          // A: 128 rows x 128B
            int id = t + i * 128;
            int row = id >> 3, c = (id & 7) << 4;
            cp16(ab + sw128(row * 128 + c), (const uint8_t*)(xa + (size_t)row * KSZ + s * BKE) + c);
        }
        #pragma unroll
        for (int i = 0; i < 16; i++) {         // B: 256 rows x 128B
            int id = t + i * 128;
            int row = id >> 3, c = (id & 7) << 4;
            cp16(bbse + sw128(row * 128 + c), (const uint8_t*)(yb + (size_t)row * KSZ + s * BKE) + c);
        }
        asm volatile("cp.async.commit_group;" ::: "memory");
    };

    // issue first stage BEFORE the (possibly blocking) TMEM alloc
    loadstage(0, 0);

    if (wid == 0) {
        asm volatile("tcgen05.alloc.cta_group::1.sync.aligned.shared::cta.b32 [%0], %1;"
                     :: "r"(sb + SM_TMEMP), "r"(256u) : "memory");
        asm volatile("tcgen05.relinquish_alloc_permit.cta_group::1.sync.aligned;" ::: "memory");
    }
    if (t == 0) { mbar_init(sb + SM_MBAR0, 1); mbar_init(sb + SM_MBAR1, 1); }
    __syncthreads();
    uint32_t tmem;
    asm volatile("ld.shared.b32 %0, [%1];" : "=r"(tmem) : "r"(sb + SM_TMEMP));

    int ph0 = 0, ph1 = 0;

    for (int s = 0; s < NSTG; s++) {
        const int buf = s & 1;
        if (s + 1 < NSTG) {
            const int nb = buf ^ 1;
            if (s + 1 >= 2) {    // nb consumed by mma of stage s-1
                if (nb == 0) { mbar_wait(sb + SM_MBAR0, ph0); ph0 ^= 1; }
                else         { mbar_wait(sb + SM_MBAR1, ph1); ph1 ^= 1; }
            }
            loadstage(s + 1, nb);
            asm volatile("cp.async.wait_group 1;" ::: "memory");
        } else {
            asm volatile("cp.async.wait_group 0;" ::: "memory");
        }
        __syncthreads();
        asm volatile("fence.proxy.async.shared::cta;" ::: "memory");

        if (wid == 0) {
            asm volatile("tcgen05.fence::after_thread_sync;" ::: "memory");
            if (elect_one()) {
                uint64_t ad = smem_desc(sb + SM_A(buf));
                uint64_t bd = smem_desc(sb + SM_B(buf));
                #pragma unroll
                for (int k = 0; k < 4; k++) {  // 4 x K=16 per 128B stage
                    mma_bf16(tmem, ad + k * 2, bd + k * 2, (uint32_t)(s * 4 + k));
                }
                asm volatile("tcgen05.commit.cta_group::1.mbarrier::arrive::one.shared::cluster.b64 [%0];"
                             :: "r"(sb + (buf ? SM_MBAR1 : SM_MBAR0)) : "memory");
            }
        }
    }

    // stage 15 used buf1; its commit covers all prior mma
    mbar_wait(sb + SM_MBAR1, ph1);
    asm volatile("tcgen05.fence::after_thread_sync;" ::: "memory");
    __syncthreads();

    const float sc = xs[0] * ys[0];
    float* tile = (float*)(smem + wid * 4352);   // per-warp 32x33 transpose tile

    #pragma unroll 1
    for (int chunk = 0; chunk < BNG / 32; chunk++) {
        uint32_t d[32];
        asm volatile(
            "tcgen05.ld.sync.aligned.32x32b.x32.b32 "
            "{%0,%1,%2,%3,%4,%5,%6,%7,%8,%9,%10,%11,%12,%13,%14,%15,"
            "%16,%17,%18,%19,%20,%21,%22,%23,%24,%25,%26,%27,%28,%29,%30,%31}, [%32];"
            : "=r"(d[0]), "=r"(d[1]), "=r"(d[2]), "=r"(d[3]), "=r"(d[4]), "=r"(d[5]), "=r"(d[6]), "=r"(d[7]),
              "=r"(d[8]), "=r"(d[9]), "=r"(d[10]), "=r"(d[11]), "=r"(d[12]), "=r"(d[13]), "=r"(d[14]), "=r"(d[15]),
              "=r"(d[16]), "=r"(d[17]), "=r"(d[18]), "=r"(d[19]), "=r"(d[20]), "=r"(d[21]), "=r"(d[22]), "=r"(d[23]),
              "=r"(d[24]), "=r"(d[25]), "=r"(d[26]), "=r"(d[27]), "=r"(d[28]), "=r"(d[29]), "=r"(d[30]), "=r"(d[31])
            : "r"(tmem + chunk * 32));
        asm volatile("tcgen05.wait::ld.sync.aligned;" ::: "memory");

        #pragma unroll
        for (int c = 0; c < 32; c++) {
            tile[lane * 33 + c] = sc * __uint_as_float(d[c]);
        }
        __syncwarp();
        #pragma unroll
        for (int r = 0; r < 32; r++) {
            out[((size_t)z * MSZ + m0 + wid * 32 + r) * NSZ + n0 + chunk * 32 + lane] = tile[r * 33 + lane];
        }
        __syncwarp();
    }

    __syncthreads();
    if (wid == 0) {
        asm volatile("tcgen05.dealloc.cta_group::1.sync.aligned.b32 %0, %1;" :: "r"(tmem), "r"(256u));
    }
#endif
}

// ---------------------------------------------------------------------------
extern "C" void kernel_launch(void* const* d_in, const int* in_sizes, int n_in,
                              void* d_out, int out_size) {
    const void* x = nullptr;
    const void* y = nullptr;
    const float* xs = nullptr;
    const float* ys = nullptr;

    for (int i = 0; i < n_in; i++) {
        long sz = in_sizes[i];
        if (sz == (long)XELEMS) x = d_in[i];
        else if (sz == (long)YELEMS) y = d_in[i];
        else if (xs == nullptr) xs = (const float*)d_in[i];
        else if (ys == nullptr) ys = (const float*)d_in[i];
    }
    float* out = (float*)d_out;

    cudaFuncSetAttribute(gemm_tc, cudaFuncAttributeMaxDynamicSharedMemorySize, DSMEM_TC);

    probe_kernel<<<1, 32>>>(x, y);
    repack_x<<<(int)(XELEMS / 4096), 256>>>(x);
    transpose_y_kernel<<<dim3(NSZ / 128, KSZ / 32, BSZ), 256>>>(y);
    gemm_tc<<<dim3(NSZ / BNG, MSZ / BMG, G * BSZ), 128, DSMEM_TC>>>(xs, ys, out);
}